// round 11
// baseline (speedup 1.0000x reference)
#include <cuda_runtime.h>

// Problem constants
#define B_ 4
#define S_ 256
#define H_ 8
#define D_ 64
#define HID_ 512
#define M_ (B_ * S_)   // 1024 rows for all projections
#define SCALE_ 0.125f

// Scratch (allocation-free rule: __device__ globals)
__device__ float g_q[M_ * HID_];
__device__ float g_k[M_ * HID_];
__device__ float g_v[M_ * HID_];
__device__ float g_x[M_ * HID_];
__device__ float g_pre[B_ * H_ * S_ * S_];   // scale*(q.k) + attn_bias, 8MB

// ---------------------------------------------------------------------------
// Packed f32x2 helpers (sm_103a)
// ---------------------------------------------------------------------------
__device__ __forceinline__ unsigned long long pack2(float lo, float hi) {
    unsigned long long r;
    asm("mov.b64 %0, {%1, %2};" : "=l"(r) : "f"(lo), "f"(hi));
    return r;
}
__device__ __forceinline__ float2 unpack2(unsigned long long v) {
    float2 r;
    asm("mov.b64 {%0, %1}, %2;" : "=f"(r.x), "=f"(r.y) : "l"(v));
    return r;
}
__device__ __forceinline__ void ffma2(unsigned long long& d,
                                      unsigned long long a, unsigned long long b) {
    asm("fma.rn.f32x2 %0, %1, %2, %0;" : "+l"(d) : "l"(a), "l"(b));
}
__device__ __forceinline__ unsigned long long add2(unsigned long long a,
                                                   unsigned long long b) {
    unsigned long long r;
    asm("add.rn.f32x2 %0, %1, %2;" : "=l"(r) : "l"(a), "l"(b));
    return r;
}
__device__ __forceinline__ unsigned long long mul2(unsigned long long a,
                                                   unsigned long long b) {
    unsigned long long r;
    asm("mul.rn.f32x2 %0, %1, %2;" : "=l"(r) : "l"(a), "l"(b));
    return r;
}

struct GemmArgs {
    const float* A;
    const float* W;
    const float* bias;
    float* C;
};

// ---------------------------------------------------------------------------
// Big GEMM: C[M,N] = A @ W + bias.  128x128 tile, BK=16, 8x8/thread, f32x2.
// 3 independent GEMMs in one launch via blockIdx.z.
// ---------------------------------------------------------------------------
__global__ __launch_bounds__(256) void gemm128_bias3_kernel(
    GemmArgs g0, GemmArgs g1, GemmArgs g2, int M, int N, int K)
{
    const GemmArgs g = (blockIdx.z == 0) ? g0 : ((blockIdx.z == 1) ? g1 : g2);
    const float* __restrict__ A    = g.A;
    const float* __restrict__ W    = g.W;
    const float* __restrict__ bias = g.bias;
    float* __restrict__ C          = g.C;

    __shared__ __align__(16) float As[16][128];
    __shared__ __align__(16) float Bs[16][128];

    const int bn = blockIdx.x * 128;
    const int bm = blockIdx.y * 128;
    const int tid = threadIdx.x;
    const int tx = tid & 15;   // N micro (8 cols)
    const int ty = tid >> 4;   // M micro (8 rows)

    const int ar = tid >> 1;          // 0..127
    const int ac = (tid & 1) * 8;     // 0 or 8
    const int br = tid >> 4;          // 0..15
    const int bc = (tid & 15) * 8;    // 0..120

    unsigned long long acc[8][4] = {};

    // prefetch kb=0
    float4 pa0 = *reinterpret_cast<const float4*>(A + (size_t)(bm + ar) * K + ac);
    float4 pa1 = *reinterpret_cast<const float4*>(A + (size_t)(bm + ar) * K + ac + 4);
    float4 pb0 = *reinterpret_cast<const float4*>(W + (size_t)br * N + bn + bc);
    float4 pb1 = *reinterpret_cast<const float4*>(W + (size_t)br * N + bn + bc + 4);

    for (int kb = 0; kb < K; kb += 16) {
        As[ac + 0][ar] = pa0.x;  As[ac + 1][ar] = pa0.y;
        As[ac + 2][ar] = pa0.z;  As[ac + 3][ar] = pa0.w;
        As[ac + 4][ar] = pa1.x;  As[ac + 5][ar] = pa1.y;
        As[ac + 6][ar] = pa1.z;  As[ac + 7][ar] = pa1.w;
        *reinterpret_cast<float4*>(&Bs[br][bc])     = pb0;
        *reinterpret_cast<float4*>(&Bs[br][bc + 4]) = pb1;
        __syncthreads();

        const int kn = kb + 16;
        if (kn < K) {
            pa0 = *reinterpret_cast<const float4*>(A + (size_t)(bm + ar) * K + kn + ac);
            pa1 = *reinterpret_cast<const float4*>(A + (size_t)(bm + ar) * K + kn + ac + 4);
            pb0 = *reinterpret_cast<const float4*>(W + (size_t)(kn + br) * N + bn + bc);
            pb1 = *reinterpret_cast<const float4*>(W + (size_t)(kn + br) * N + bn + bc + 4);
        }

        #pragma unroll
        for (int kk = 0; kk < 16; kk++) {
            const float4 a0 = *reinterpret_cast<const float4*>(&As[kk][ty * 8]);
            const float4 a1 = *reinterpret_cast<const float4*>(&As[kk][ty * 8 + 4]);
            const ulonglong2 b0 = *reinterpret_cast<const ulonglong2*>(&Bs[kk][tx * 8]);
            const ulonglong2 b1 = *reinterpret_cast<const ulonglong2*>(&Bs[kk][tx * 8 + 4]);
            const unsigned long long aa[8] = {
                pack2(a0.x, a0.x), pack2(a0.y, a0.y), pack2(a0.z, a0.z), pack2(a0.w, a0.w),
                pack2(a1.x, a1.x), pack2(a1.y, a1.y), pack2(a1.z, a1.z), pack2(a1.w, a1.w)
            };
            #pragma unroll
            for (int i = 0; i < 8; i++) {
                ffma2(acc[i][0], aa[i], b0.x);
                ffma2(acc[i][1], aa[i], b0.y);
                ffma2(acc[i][2], aa[i], b1.x);
                ffma2(acc[i][3], aa[i], b1.y);
            }
        }
        __syncthreads();
    }

    const int col = bn + tx * 8;
    const float4 bb0 = *reinterpret_cast<const float4*>(bias + col);
    const float4 bb1 = *reinterpret_cast<const float4*>(bias + col + 4);
    #pragma unroll
    for (int i = 0; i < 8; i++) {
        const int row = bm + ty * 8 + i;
        const float2 c0 = unpack2(acc[i][0]);
        const float2 c1 = unpack2(acc[i][1]);
        const float2 c2 = unpack2(acc[i][2]);
        const float2 c3 = unpack2(acc[i][3]);
        float4 o0, o1;
        o0.x = c0.x + bb0.x;  o0.y = c0.y + bb0.y;
        o0.z = c1.x + bb0.z;  o0.w = c1.y + bb0.w;
        o1.x = c2.x + bb1.x;  o1.y = c2.y + bb1.y;
        o1.z = c3.x + bb1.z;  o1.w = c3.y + bb1.w;
        *reinterpret_cast<float4*>(C + (size_t)row * N + col)     = o0;
        *reinterpret_cast<float4*>(C + (size_t)row * N + col + 4) = o1;
    }
}

// ---------------------------------------------------------------------------
// Small GEMM for the O projection: 64x64 tile, BK=16, 4x4/thread (one wave).
// ---------------------------------------------------------------------------
__global__ __launch_bounds__(256) void gemm_bias_kernel(
    const float* __restrict__ A, const float* __restrict__ W,
    const float* __restrict__ bias, float* __restrict__ C,
    int M, int N, int K)
{
    __shared__ __align__(16) float As[16][64];
    __shared__ __align__(16) float Bs[16][64];

    const int bn = blockIdx.x * 64;
    const int bm = blockIdx.y * 64;
    const int tid = threadIdx.x;
    const int tx = tid & 15;
    const int ty = tid >> 4;

    const int aRow = tid >> 2;
    const int aCol = (tid & 3) * 4;
    const int bRow = tid >> 4;
    const int bCol = (tid & 15) * 4;

    unsigned long long acc2[4][2] = {};

    for (int kb = 0; kb < K; kb += 16) {
        float4 av = *reinterpret_cast<const float4*>(A + (size_t)(bm + aRow) * K + kb + aCol);
        As[aCol + 0][aRow] = av.x;
        As[aCol + 1][aRow] = av.y;
        As[aCol + 2][aRow] = av.z;
        As[aCol + 3][aRow] = av.w;
        *reinterpret_cast<float4*>(&Bs[bRow][bCol]) =
            *reinterpret_cast<const float4*>(W + (size_t)(kb + bRow) * N + bn + bCol);
        __syncthreads();

        #pragma unroll
        for (int kk = 0; kk < 16; kk++) {
            const float4 a4 = *reinterpret_cast<const float4*>(&As[kk][ty * 4]);
            const ulonglong2 b2 = *reinterpret_cast<const ulonglong2*>(&Bs[kk][tx * 4]);
            const unsigned long long aa0 = pack2(a4.x, a4.x);
            const unsigned long long aa1 = pack2(a4.y, a4.y);
            const unsigned long long aa2 = pack2(a4.z, a4.z);
            const unsigned long long aa3 = pack2(a4.w, a4.w);
            ffma2(acc2[0][0], aa0, b2.x);  ffma2(acc2[0][1], aa0, b2.y);
            ffma2(acc2[1][0], aa1, b2.x);  ffma2(acc2[1][1], aa1, b2.y);
            ffma2(acc2[2][0], aa2, b2.x);  ffma2(acc2[2][1], aa2, b2.y);
            ffma2(acc2[3][0], aa3, b2.x);  ffma2(acc2[3][1], aa3, b2.y);
        }
        __syncthreads();
    }

    const int col = bn + tx * 4;
    const float4 bb = *reinterpret_cast<const float4*>(bias + col);
    #pragma unroll
    for (int i = 0; i < 4; i++) {
        const int row = bm + ty * 4 + i;
        const float2 c01 = unpack2(acc2[i][0]);
        const float2 c23 = unpack2(acc2[i][1]);
        float4 o;
        o.x = c01.x + bb.x;
        o.y = c01.y + bb.y;
        o.z = c23.x + bb.z;
        o.w = c23.y + bb.w;
        *reinterpret_cast<float4*>(C + (size_t)row * N + col) = o;
    }
}

// ---------------------------------------------------------------------------
// QK precompute: pre[b,h,s,t] = scale*(q_s . k_t) + attn_bias[b,h,s,t]
// One CTA per (64 s) x (64 t) x (b,h). Tiny, L2-resident.
// ---------------------------------------------------------------------------
__global__ __launch_bounds__(256) void qk_pre_kernel(
    const float* __restrict__ qh, const float* __restrict__ kh,
    const float* __restrict__ ab, float* __restrict__ pre)
{
    const int bh = blockIdx.z;
    const int b  = bh >> 3;
    const int t0 = blockIdx.x * 64;
    const int s0 = blockIdx.y * 64;
    const int h  = bh & 7;

    __shared__ __align__(16) float Qs[64][68];
    __shared__ __align__(16) float Ks[64][68];

    const int tid = threadIdx.x;
    const int r = tid >> 4;
    const int c = (tid & 15) * 4;
    #pragma unroll
    for (int j = 0; j < 4; j++) {
        const int rr = r + 16 * j;
        *reinterpret_cast<float4*>(&Qs[rr][c]) =
            *reinterpret_cast<const float4*>(qh + (size_t)(b * S_ + s0 + rr) * HID_ + h * D_ + c);
        *reinterpret_cast<float4*>(&Ks[rr][c]) =
            *reinterpret_cast<const float4*>(kh + (size_t)(b * S_ + t0 + rr) * HID_ + h * D_ + c);
    }
    __syncthreads();

    const int tx = tid & 15;   // t micro (4)
    const int ty = tid >> 4;   // s micro (4)
    float acc[4][4] = {};

    #pragma unroll
    for (int d = 0; d < D_; d += 4) {
        float4 qa[4], ka[4];
        #pragma unroll
        for (int i = 0; i < 4; i++) {
            qa[i] = *reinterpret_cast<const float4*>(&Qs[ty * 4 + i][d]);
            ka[i] = *reinterpret_cast<const float4*>(&Ks[tx * 4 + i][d]);
        }
        #pragma unroll
        for (int i = 0; i < 4; i++)
            #pragma unroll
            for (int j = 0; j < 4; j++)
                acc[i][j] += qa[i].x * ka[j].x + qa[i].y * ka[j].y
                           + qa[i].z * ka[j].z + qa[i].w * ka[j].w;
    }

    #pragma unroll
    for (int i = 0; i < 4; i++) {
        const int srow = s0 + ty * 4 + i;
        const size_t base = ((size_t)bh * S_ + srow) * S_ + t0 + tx * 4;
        const float4 abv = *reinterpret_cast<const float4*>(ab + base);
        float4 o;
        o.x = acc[i][0] * SCALE_ + abv.x;
        o.y = acc[i][1] * SCALE_ + abv.y;
        o.z = acc[i][2] * SCALE_ + abv.z;
        o.w = acc[i][3] * SCALE_ + abv.w;
        *reinterpret_cast<float4*>(pre + base) = o;
    }
}

// ---------------------------------------------------------------------------
// Fused GRPE attention (q.k hoisted): one CTA per (b,h,s) row.
//   score[t] = (q_s.spq[s,t] + k_s.spk[s,t]) * scale + pre[s,t]
// ---------------------------------------------------------------------------
__global__ __launch_bounds__(256, 5) void attn_grpe_kernel(
    const float* __restrict__ qh, const float* __restrict__ kh,
    const float* __restrict__ vh, const float* __restrict__ pre,
    const float* __restrict__ spq, const float* __restrict__ spk,
    float* __restrict__ xo)
{
    const int s = blockIdx.x;
    const int h = blockIdx.y;
    const int b = blockIdx.z;
    const int tid = threadIdx.x;
    const int lane = tid & 31;
    const int w = tid >> 5;
    const int half = lane >> 4;
    const int l16 = lane & 15;

    __shared__ __align__(16) float sh_q[D_];
    __shared__ __align__(16) float sh_k[D_];
    __shared__ float sc[S_];
    __shared__ float sb[S_];
    __shared__ __align__(16) float pvp[16][D_];
    __shared__ float redm[8], reds[8];

    const int bh = b * H_ + h;
    const float* qrow = qh + (size_t)(b * S_ + s) * HID_ + h * D_;
    const float* krow = kh + (size_t)(b * S_ + s) * HID_ + h * D_;
    if (tid < D_)            sh_q[tid]       = qrow[tid];
    else if (tid < 2 * D_)   sh_k[tid - D_]  = krow[tid - D_];
    sb[tid] = pre[((size_t)bh * S_ + s) * S_ + tid];
    __syncthreads();

    const float4 q4 = reinterpret_cast<const float4*>(sh_q)[l16];
    const float4 k4 = reinterpret_cast<const float4*>(sh_k)[l16];
    const unsigned long long q01 = pack2(q4.x, q4.y);
    const unsigned long long q23 = pack2(q4.z, q4.w);
    const unsigned long long k01 = pack2(k4.x, k4.y);
    const unsigned long long k23 = pack2(k4.z, k4.w);

    const size_t rowbase = ((size_t)bh * S_ + s) * (size_t)(S_ * D_);
    const ulonglong2* spq2 = reinterpret_cast<const ulonglong2*>(spq + rowbase);
    const ulonglong2* spk2 = reinterpret_cast<const ulonglong2*>(spk + rowbase);

    // Each warp covers t in [w*32, w*32+32), 2 t's per iteration.
    #pragma unroll 8
    for (int i = 0; i < 16; i++) {
        const int t = w * 32 + 2 * i + half;
        const int off = t * (D_ / 4) + l16;          // 16B-granule index
        const ulonglong2 aq = spq2[off];
        const ulonglong2 ak = spk2[off];
        unsigned long long p2 = mul2(q01, aq.x);
        ffma2(p2, q23, aq.y);
        ffma2(p2, k01, ak.x);
        ffma2(p2, k23, ak.y);
        const float2 pf = unpack2(p2);
        float p = pf.x + pf.y;
        p += __shfl_xor_sync(0xffffffffu, p, 8);
        p += __shfl_xor_sync(0xffffffffu, p, 4);
        p += __shfl_xor_sync(0xffffffffu, p, 2);
        p += __shfl_xor_sync(0xffffffffu, p, 1);
        if (l16 == 0) sc[t] = p * SCALE_ + sb[t];
    }
    __syncthreads();

    // ---- softmax over 256 scores ----
    const float v0 = sc[tid];
    float m = v0;
    #pragma unroll
    for (int o = 16; o > 0; o >>= 1) m = fmaxf(m, __shfl_xor_sync(0xffffffffu, m, o));
    if (lane == 0) redm[w] = m;
    __syncthreads();
    float gm = redm[0];
    #pragma unroll
    for (int j = 1; j < 8; j++) gm = fmaxf(gm, redm[j]);

    const float e = __expf(v0 - gm);
    sc[tid] = e;
    float sum = e;
    #pragma unroll
    for (int o = 16; o > 0; o >>= 1) sum += __shfl_xor_sync(0xffffffffu, sum, o);
    if (lane == 0) reds[w] = sum;
    __syncthreads();
    float tot = reds[0];
    #pragma unroll
    for (int j = 1; j < 8; j++) tot += reds[j];
    const float inv = 1.0f / tot;

    // ---- P @ V : 16 groups of 16 threads ----
    const int g  = tid >> 4;
    const int ld = tid & 15;
    const float* vbase = vh + (size_t)(b * S_) * HID_ + h * D_;
    unsigned long long acc01 = 0ull, acc23 = 0ull;
    #pragma unroll
    for (int i = 0; i < 16; i++) {
        const int t = g * 16 + i;
        const float wt = sc[t];
        const unsigned long long w2 = pack2(wt, wt);
        const ulonglong2 v2 = reinterpret_cast<const ulonglong2*>(
            vbase + (size_t)t * HID_)[ld];
        ffma2(acc01, w2, v2.x);
        ffma2(acc23, w2, v2.y);
    }
    {
        const float2 a01 = unpack2(acc01);
        const float2 a23 = unpack2(acc23);
        float4 o; o.x = a01.x; o.y = a01.y; o.z = a23.x; o.w = a23.y;
        *reinterpret_cast<float4*>(&pvp[g][ld * 4]) = o;
    }
    __syncthreads();

    const int d  = tid & 63;
    const int gq = tid >> 6;
    const float part = pvp[gq * 4 + 0][d] + pvp[gq * 4 + 1][d]
                     + pvp[gq * 4 + 2][d] + pvp[gq * 4 + 3][d];
    __syncthreads();
    pvp[gq][d] = part;
    __syncthreads();

    if (tid < D_) {
        const float r = (pvp[0][tid] + pvp[1][tid] + pvp[2][tid] + pvp[3][tid]) * inv;
        xo[(size_t)(b * S_ + s) * HID_ + h * D_ + tid] = r;
    }
}

// ---------------------------------------------------------------------------
// Launch
// ---------------------------------------------------------------------------
extern "C" void kernel_launch(void* const* d_in, const int* in_sizes, int n_in,
                              void* d_out, int out_size)
{
    const float* q    = (const float*)d_in[0];
    const float* k    = (const float*)d_in[1];
    const float* v    = (const float*)d_in[2];
    const float* ab   = (const float*)d_in[3];
    const float* spq  = (const float*)d_in[4];
    const float* spk  = (const float*)d_in[5];
    const float* Wq   = (const float*)d_in[6];
    const float* bq   = (const float*)d_in[7];
    const float* Wk   = (const float*)d_in[8];
    const float* bk   = (const float*)d_in[9];
    const float* Wv   = (const float*)d_in[10];
    const float* bv   = (const float*)d_in[11];
    const float* Wo   = (const float*)d_in[12];
    const float* bo   = (const float*)d_in[13];
    float* out        = (float*)d_out;

    void *pq = nullptr, *pk = nullptr, *pv = nullptr, *px = nullptr, *pp = nullptr;
    cudaGetSymbolAddress(&pq, g_q);
    cudaGetSymbolAddress(&pk, g_k);
    cudaGetSymbolAddress(&pv, g_v);
    cudaGetSymbolAddress(&px, g_x);
    cudaGetSymbolAddress(&pp, g_pre);

    // Fused Q/K/V projections: one launch, 96 CTAs of 128x128 tiles.
    GemmArgs gq_args = { q, Wq, bq, (float*)pq };
    GemmArgs gk_args = { k, Wk, bk, (float*)pk };
    GemmArgs gv_args = { v, Wv, bv, (float*)pv };
    const dim3 gqkv(HID_ / 128, M_ / 128, 3);   // (4, 8, 3)
    gemm128_bias3_kernel<<<gqkv, 256>>>(gq_args, gk_args, gv_args, M_, HID_, HID_);

    // pre = scale*(q.k) + attn_bias
    const dim3 gp(S_ / 64, S_ / 64, B_ * H_);   // (4, 4, 32)
    qk_pre_kernel<<<gp, 256>>>((const float*)pq, (const float*)pk, ab, (float*)pp);

    const dim3 ga(S_, H_, B_);                  // 8192 blocks
    attn_grpe_kernel<<<ga, 256>>>((const float*)pq, (const float*)pk, (const float*)pv,
                                  (const float*)pp, spq, spk, (float*)px);

    // Output projection: 64x64 tiles, 128 CTAs (full wave).
    const dim3 go(HID_ / 64, M_ / 64);
    gemm_bias_kernel<<<go, 256>>>((const float*)px, Wo, bo, out, M_, HID_, HID_);
}

// round 12
// speedup vs baseline: 1.0341x; 1.0341x over previous
#include <cuda_runtime.h>

// Problem constants
#define B_ 4
#define S_ 256
#define H_ 8
#define D_ 64
#define HID_ 512
#define M_ (B_ * S_)   // 1024 rows for all projections
#define SCALE_ 0.125f
#define NR_ 4          // s-rows per attention CTA

// Scratch (allocation-free rule: __device__ globals)
__device__ float g_q[M_ * HID_];
__device__ float g_k[M_ * HID_];
__device__ float g_v[M_ * HID_];
__device__ float g_x[M_ * HID_];
__device__ float g_part[6 * M_ * HID_];   // split-K partials (max 6 x 2MB)

// ---------------------------------------------------------------------------
// Packed f32x2 helpers (sm_103a)
// ---------------------------------------------------------------------------
__device__ __forceinline__ unsigned long long pack2(float lo, float hi) {
    unsigned long long r;
    asm("mov.b64 %0, {%1, %2};" : "=l"(r) : "f"(lo), "f"(hi));
    return r;
}
__device__ __forceinline__ float2 unpack2(unsigned long long v) {
    float2 r;
    asm("mov.b64 {%0, %1}, %2;" : "=f"(r.x), "=f"(r.y) : "l"(v));
    return r;
}
__device__ __forceinline__ void ffma2(unsigned long long& d,
                                      unsigned long long a, unsigned long long b) {
    asm("fma.rn.f32x2 %0, %1, %2, %0;" : "+l"(d) : "l"(a), "l"(b));
}
__device__ __forceinline__ unsigned long long add2(unsigned long long a,
                                                   unsigned long long b) {
    unsigned long long r;
    asm("add.rn.f32x2 %0, %1, %2;" : "=l"(r) : "l"(a), "l"(b));
    return r;
}
__device__ __forceinline__ unsigned long long mul2(unsigned long long a,
                                                   unsigned long long b) {
    unsigned long long r;
    asm("mul.rn.f32x2 %0, %1, %2;" : "=l"(r) : "l"(a), "l"(b));
    return r;
}

struct GemmPtrs {
    const float* A[3];
    const float* W[3];
};
struct RedPtrs {
    const float* bias[3];
    float* out[3];
};

// ---------------------------------------------------------------------------
// Split-K GEMM partial: 64x64 tile, BK=16, 4x4/thread, f32x2.
// blockIdx.z = gemm * nsl + slice. Writes partial (no bias) to
// part + z * (M_*HID_).
// ---------------------------------------------------------------------------
__global__ __launch_bounds__(256) void gemm64_part_kernel(
    GemmPtrs gp, float* __restrict__ part, int nsl, int klen, int N, int K)
{
    const int z    = blockIdx.z;
    const int gemm = z / nsl;
    const int sl   = z - gemm * nsl;
    const float* __restrict__ A = gp.A[gemm];
    const float* __restrict__ W = gp.W[gemm];
    float* __restrict__ C = part + (size_t)z * (M_ * HID_);
    const int k0 = sl * klen;

    __shared__ __align__(16) float As[16][64];
    __shared__ __align__(16) float Bs[16][64];

    const int bn = blockIdx.x * 64;
    const int bm = blockIdx.y * 64;
    const int tid = threadIdx.x;
    const int tx = tid & 15;
    const int ty = tid >> 4;

    const int aRow = tid >> 2;
    const int aCol = (tid & 3) * 4;
    const int bRow = tid >> 4;
    const int bCol = (tid & 15) * 4;

    unsigned long long acc2[4][2] = {};

    for (int kb = k0; kb < k0 + klen; kb += 16) {
        float4 av = *reinterpret_cast<const float4*>(A + (size_t)(bm + aRow) * K + kb + aCol);
        As[aCol + 0][aRow] = av.x;
        As[aCol + 1][aRow] = av.y;
        As[aCol + 2][aRow] = av.z;
        As[aCol + 3][aRow] = av.w;
        *reinterpret_cast<float4*>(&Bs[bRow][bCol]) =
            *reinterpret_cast<const float4*>(W + (size_t)(kb + bRow) * N + bn + bCol);
        __syncthreads();

        #pragma unroll
        for (int kk = 0; kk < 16; kk++) {
            const float4 a4 = *reinterpret_cast<const float4*>(&As[kk][ty * 4]);
            const ulonglong2 b2 = *reinterpret_cast<const ulonglong2*>(&Bs[kk][tx * 4]);
            const unsigned long long aa0 = pack2(a4.x, a4.x);
            const unsigned long long aa1 = pack2(a4.y, a4.y);
            const unsigned long long aa2 = pack2(a4.z, a4.z);
            const unsigned long long aa3 = pack2(a4.w, a4.w);
            ffma2(acc2[0][0], aa0, b2.x);  ffma2(acc2[0][1], aa0, b2.y);
            ffma2(acc2[1][0], aa1, b2.x);  ffma2(acc2[1][1], aa1, b2.y);
            ffma2(acc2[2][0], aa2, b2.x);  ffma2(acc2[2][1], aa2, b2.y);
            ffma2(acc2[3][0], aa3, b2.x);  ffma2(acc2[3][1], aa3, b2.y);
        }
        __syncthreads();
    }

    const int col = bn + tx * 4;
    #pragma unroll
    for (int i = 0; i < 4; i++) {
        const int row = bm + ty * 4 + i;
        const float2 c01 = unpack2(acc2[i][0]);
        const float2 c23 = unpack2(acc2[i][1]);
        float4 o;
        o.x = c01.x;  o.y = c01.y;  o.z = c23.x;  o.w = c23.y;
        *reinterpret_cast<float4*>(C + (size_t)row * N + col) = o;
    }
}

// ---------------------------------------------------------------------------
// Split-K reduce + bias: out[g] = sum_j part[g*nsl + j] + bias[g]
// grid.x = (M_*HID_/4)/256 = 512, grid.y = #gemms
// ---------------------------------------------------------------------------
__global__ __launch_bounds__(256) void reduce_bias_kernel(
    const float* __restrict__ part, RedPtrs rp, int nsl)
{
    const int g = blockIdx.y;
    const int i = blockIdx.x * 256 + threadIdx.x;        // float4 index
    const size_t stride4 = (size_t)(M_ * HID_) / 4;
    const float4* p = reinterpret_cast<const float4*>(part) + (size_t)g * nsl * stride4;

    float4 s = p[i];
    for (int j = 1; j < nsl; j++) {
        const float4 t = p[(size_t)j * stride4 + i];
        s.x += t.x;  s.y += t.y;  s.z += t.z;  s.w += t.w;
    }
    const float4 b4 = reinterpret_cast<const float4*>(rp.bias[g])[i & (HID_ / 4 - 1)];
    s.x += b4.x;  s.y += b4.y;  s.z += b4.z;  s.w += b4.w;
    reinterpret_cast<float4*>(rp.out[g])[i] = s;
}

// ---------------------------------------------------------------------------
// Fused GRPE attention, NR_=4 s-rows per CTA (same b,h):
//   score_r[t] = (q_r.(k_t+spq[r,t]) + k_r.spk[r,t]) * scale + abias[r,t]
//   softmax per row, then out_r[d] = sum_t p_r[t] * v[t,d]
// k_t loaded once per t, shared by 4 rows. PV: warp-per-(row, t-half),
// v rows shared 4x across rows, no cross-lane reductions.
// ---------------------------------------------------------------------------
__global__ __launch_bounds__(256, 4) void attn_grpe4_kernel(
    const float* __restrict__ qh, const float* __restrict__ kh,
    const float* __restrict__ vh, const float* __restrict__ abias,
    const float* __restrict__ spq, const float* __restrict__ spk,
    float* __restrict__ xo)
{
    const int s0 = blockIdx.x * NR_;
    const int h  = blockIdx.y;
    const int b  = blockIdx.z;
    const int bh = b * H_ + h;
    const int tid = threadIdx.x;
    const int lane = tid & 31;
    const int w = tid >> 5;
    const int half = lane >> 4;
    const int l16 = lane & 15;

    __shared__ __align__(16) float sq[NR_][D_];
    __shared__ __align__(16) float sk[NR_][D_];
    __shared__ float sc[NR_][S_];
    __shared__ float sb[NR_][S_];
    __shared__ __align__(16) float pvp[8][D_];
    __shared__ float redm[NR_][8], reds[NR_][8];

    // ---- prologue: q/k rows + bias rows ----
    {
        const int r = tid >> 6;          // 0..3
        const int d = tid & 63;
        sq[r][d] = qh[(size_t)(b * S_ + s0 + r) * HID_ + h * D_ + d];
        sk[r][d] = kh[(size_t)(b * S_ + s0 + r) * HID_ + h * D_ + d];
    }
    #pragma unroll
    for (int r = 0; r < NR_; r++)
        sb[r][tid] = abias[((size_t)(bh * S_) + s0 + r) * S_ + tid];
    __syncthreads();

    // ---- scores: warp w covers t in [w*32, w*32+32), half-warp per t ----
    const ulonglong2* sq2 = reinterpret_cast<const ulonglong2*>(&sq[0][0]);
    const ulonglong2* sk2 = reinterpret_cast<const ulonglong2*>(&sk[0][0]);
    const ulonglong2* aqp[NR_];
    const ulonglong2* akp[NR_];
    #pragma unroll
    for (int r = 0; r < NR_; r++) {
        const size_t rb = ((size_t)(bh * S_) + s0 + r) * (size_t)(S_ * D_);
        aqp[r] = reinterpret_cast<const ulonglong2*>(spq + rb);
        akp[r] = reinterpret_cast<const ulonglong2*>(spk + rb);
    }

    #pragma unroll 2
    for (int i = 0; i < 16; i++) {
        const int t = w * 32 + 2 * i + half;
        const int off = t * 16 + l16;                    // 16B-granule index
        const ulonglong2 kk = reinterpret_cast<const ulonglong2*>(
            kh + (size_t)(b * S_ + t) * HID_ + h * D_)[l16];
        #pragma unroll
        for (int r = 0; r < NR_; r++) {
            const ulonglong2 aq = aqp[r][off];
            const ulonglong2 ak = akp[r][off];
            const ulonglong2 qv = sq2[r * 16 + l16];     // broadcast LDS
            const ulonglong2 kv = sk2[r * 16 + l16];
            unsigned long long p2 = mul2(qv.x, add2(kk.x, aq.x));
            ffma2(p2, qv.y, add2(kk.y, aq.y));
            ffma2(p2, kv.x, ak.x);
            ffma2(p2, kv.y, ak.y);
            const float2 pf = unpack2(p2);
            float p = pf.x + pf.y;
            p += __shfl_xor_sync(0xffffffffu, p, 8);
            p += __shfl_xor_sync(0xffffffffu, p, 4);
            p += __shfl_xor_sync(0xffffffffu, p, 2);
            p += __shfl_xor_sync(0xffffffffu, p, 1);
            if (l16 == 0) sc[r][t] = p * SCALE_ + sb[r][t];
        }
    }
    __syncthreads();

    // ---- softmax (4 rows, thread owns t=tid in each row) ----
    #pragma unroll
    for (int r = 0; r < NR_; r++) {
        float m = sc[r][tid];
        #pragma unroll
        for (int o = 16; o > 0; o >>= 1) m = fmaxf(m, __shfl_xor_sync(0xffffffffu, m, o));
        if (lane == 0) redm[r][w] = m;
    }
    __syncthreads();
    #pragma unroll
    for (int r = 0; r < NR_; r++) {
        float gm = redm[r][0];
        #pragma unroll
        for (int j = 1; j < 8; j++) gm = fmaxf(gm, redm[r][j]);
        const float e = __expf(sc[r][tid] - gm);
        sc[r][tid] = e;
        float sum = e;
        #pragma unroll
        for (int o = 16; o > 0; o >>= 1) sum += __shfl_xor_sync(0xffffffffu, sum, o);
        if (lane == 0) reds[r][w] = sum;
    }
    __syncthreads();

    // ---- P @ V : warp w -> row (w>>1), t-half (w&1); lane owns float2 of d ----
    {
        const int r  = w >> 1;
        const int th = w & 1;
        float tot = reds[r][0];
        #pragma unroll
        for (int j = 1; j < 8; j++) tot += reds[r][j];
        const float inv = 1.0f / tot;

        const float* vb = vh + (size_t)(b * S_) * HID_ + h * D_ + 2 * lane;
        unsigned long long acc = 0ull;
        #pragma unroll 8
        for (int i = 0; i < 128; i++) {
            const int t = th * 128 + i;
            const float wt = sc[r][t];
            const unsigned long long v2 =
                *reinterpret_cast<const unsigned long long*>(vb + (size_t)t * HID_);
            ffma2(acc, pack2(wt, wt), v2);
        }
        const float2 a2 = unpack2(acc);
        pvp[w][2 * lane]     = a2.x * inv;
        pvp[w][2 * lane + 1] = a2.y * inv;
    }
    __syncthreads();

    // combine the two t-halves per row and write out
    {
        const int r = tid >> 6;
        const int d = tid & 63;
        const float o = pvp[2 * r][d] + pvp[2 * r + 1][d];
        xo[(size_t)(b * S_ + s0 + r) * HID_ + h * D_ + d] = o;
    }
}

// ---------------------------------------------------------------------------
// Launch
// ---------------------------------------------------------------------------
extern "C" void kernel_launch(void* const* d_in, const int* in_sizes, int n_in,
                              void* d_out, int out_size)
{
    const float* q    = (const float*)d_in[0];
    const float* k    = (const float*)d_in[1];
    const float* v    = (const float*)d_in[2];
    const float* ab   = (const float*)d_in[3];
    const float* spq  = (const float*)d_in[4];
    const float* spk  = (const float*)d_in[5];
    const float* Wq   = (const float*)d_in[6];
    const float* bq   = (const float*)d_in[7];
    const float* Wk   = (const float*)d_in[8];
    const float* bk   = (const float*)d_in[9];
    const float* Wv   = (const float*)d_in[10];
    const float* bv   = (const float*)d_in[11];
    const float* Wo   = (const float*)d_in[12];
    const float* bo   = (const float*)d_in[13];
    float* out        = (float*)d_out;

    void *pq = nullptr, *pk = nullptr, *pv = nullptr, *px = nullptr, *pp = nullptr;
    cudaGetSymbolAddress(&pq, g_q);
    cudaGetSymbolAddress(&pk, g_k);
    cudaGetSymbolAddress(&pv, g_v);
    cudaGetSymbolAddress(&px, g_x);
    cudaGetSymbolAddress(&pp, g_part);

    // ---- QKV projections: split-K2, 3 GEMMs in one launch (768 CTAs) ----
    GemmPtrs qkv;
    qkv.A[0] = q;  qkv.A[1] = k;  qkv.A[2] = v;
    qkv.W[0] = Wq; qkv.W[1] = Wk; qkv.W[2] = Wv;
    gemm64_part_kernel<<<dim3(HID_ / 64, M_ / 64, 6), 256>>>(
        qkv, (float*)pp, 2, 256, HID_, HID_);

    RedPtrs r1;
    r1.bias[0] = bq; r1.bias[1] = bk; r1.bias[2] = bv;
    r1.out[0] = (float*)pq; r1.out[1] = (float*)pk; r1.out[2] = (float*)pv;
    reduce_bias_kernel<<<dim3(M_ * HID_ / 4 / 256, 3), 256>>>((const float*)pp, r1, 2);

    // ---- attention: 4 s-rows per CTA ----
    const dim3 ga(S_ / NR_, H_, B_);    // (64, 8, 4) = 2048 CTAs
    attn_grpe4_kernel<<<ga, 256>>>((const float*)pq, (const float*)pk, (const float*)pv,
                                   ab, spq, spk, (float*)px);

    // ---- O projection: split-K4 (512 CTAs) ----
    GemmPtrs og;
    og.A[0] = (const float*)px; og.A[1] = og.A[0]; og.A[2] = og.A[0];
    og.W[0] = Wo; og.W[1] = Wo; og.W[2] = Wo;
    gemm64_part_kernel<<<dim3(HID_ / 64, M_ / 64, 4), 256>>>(
        og, (float*)pp, 4, 128, HID_, HID_);

    RedPtrs r2;
    r2.bias[0] = bo; r2.bias[1] = bo; r2.bias[2] = bo;
    r2.out[0] = out; r2.out[1] = out; r2.out[2] = out;
    reduce_bias_kernel<<<dim3(M_ * HID_ / 4 / 256, 1), 256>>>((const float*)pp, r2, 4);
}

// round 14
// speedup vs baseline: 1.1674x; 1.1289x over previous
#include <cuda_runtime.h>
#include <cstdint>

// Problem constants
#define B_ 4
#define S_ 256
#define H_ 8
#define D_ 64
#define HID_ 512
#define M_ (B_ * S_)   // 1024 rows for all projections
#define SCALE_ 0.125f
#define TT_ 32         // t-tile per pipeline stage

// Scratch (allocation-free rule: __device__ globals)
__device__ float g_q[M_ * HID_];
__device__ float g_k[M_ * HID_];
__device__ float g_v[M_ * HID_];
__device__ float g_x[M_ * HID_];
__device__ float g_part[6 * M_ * HID_];   // split-K partials (max 6 x 2MB)

// ---------------------------------------------------------------------------
// Packed f32x2 helpers (sm_103a)
// ---------------------------------------------------------------------------
__device__ __forceinline__ unsigned long long pack2(float lo, float hi) {
    unsigned long long r;
    asm("mov.b64 %0, {%1, %2};" : "=l"(r) : "f"(lo), "f"(hi));
    return r;
}
__device__ __forceinline__ float2 unpack2(unsigned long long v) {
    float2 r;
    asm("mov.b64 {%0, %1}, %2;" : "=f"(r.x), "=f"(r.y) : "l"(v));
    return r;
}
__device__ __forceinline__ void ffma2(unsigned long long& d,
                                      unsigned long long a, unsigned long long b) {
    asm("fma.rn.f32x2 %0, %1, %2, %0;" : "+l"(d) : "l"(a), "l"(b));
}
__device__ __forceinline__ unsigned long long add2(unsigned long long a,
                                                   unsigned long long b) {
    unsigned long long r;
    asm("add.rn.f32x2 %0, %1, %2;" : "=l"(r) : "l"(a), "l"(b));
    return r;
}
__device__ __forceinline__ unsigned long long mul2(unsigned long long a,
                                                   unsigned long long b) {
    unsigned long long r;
    asm("mul.rn.f32x2 %0, %1, %2;" : "=l"(r) : "l"(a), "l"(b));
    return r;
}
__device__ __forceinline__ void cpasync16(unsigned int saddr, const void* g) {
    asm volatile("cp.async.cg.shared.global [%0], [%1], 16;" :: "r"(saddr), "l"(g));
}
__device__ __forceinline__ unsigned int smem_u32(const void* p) {
    return (unsigned int)__cvta_generic_to_shared(p);
}

struct GemmPtrs {
    const float* A[3];
    const float* W[3];
};
struct RedPtrs {
    const float* bias[3];
    float* out[3];
};

// ---------------------------------------------------------------------------
// Split-K GEMM partial: 64x64 tile, BK=16, 4x4/thread, f32x2.
// blockIdx.z = gemm * nsl + slice.
// ---------------------------------------------------------------------------
__global__ __launch_bounds__(256) void gemm64_part_kernel(
    GemmPtrs gp, float* __restrict__ part, int nsl, int klen, int N, int K)
{
    const int z    = blockIdx.z;
    const int gemm = z / nsl;
    const int sl   = z - gemm * nsl;
    const float* __restrict__ A = gp.A[gemm];
    const float* __restrict__ W = gp.W[gemm];
    float* __restrict__ C = part + (size_t)z * (M_ * HID_);
    const int k0 = sl * klen;

    __shared__ __align__(16) float As[16][64];
    __shared__ __align__(16) float Bs[16][64];

    const int bn = blockIdx.x * 64;
    const int bm = blockIdx.y * 64;
    const int tid = threadIdx.x;
    const int tx = tid & 15;
    const int ty = tid >> 4;

    const int aRow = tid >> 2;
    const int aCol = (tid & 3) * 4;
    const int bRow = tid >> 4;
    const int bCol = (tid & 15) * 4;

    unsigned long long acc2[4][2] = {};

    for (int kb = k0; kb < k0 + klen; kb += 16) {
        float4 av = *reinterpret_cast<const float4*>(A + (size_t)(bm + aRow) * K + kb + aCol);
        As[aCol + 0][aRow] = av.x;
        As[aCol + 1][aRow] = av.y;
        As[aCol + 2][aRow] = av.z;
        As[aCol + 3][aRow] = av.w;
        *reinterpret_cast<float4*>(&Bs[bRow][bCol]) =
            *reinterpret_cast<const float4*>(W + (size_t)(kb + bRow) * N + bn + bCol);
        __syncthreads();

        #pragma unroll
        for (int kk = 0; kk < 16; kk++) {
            const float4 a4 = *reinterpret_cast<const float4*>(&As[kk][ty * 4]);
            const ulonglong2 b2 = *reinterpret_cast<const ulonglong2*>(&Bs[kk][tx * 4]);
            const unsigned long long aa0 = pack2(a4.x, a4.x);
            const unsigned long long aa1 = pack2(a4.y, a4.y);
            const unsigned long long aa2 = pack2(a4.z, a4.z);
            const unsigned long long aa3 = pack2(a4.w, a4.w);
            ffma2(acc2[0][0], aa0, b2.x);  ffma2(acc2[0][1], aa0, b2.y);
            ffma2(acc2[1][0], aa1, b2.x);  ffma2(acc2[1][1], aa1, b2.y);
            ffma2(acc2[2][0], aa2, b2.x);  ffma2(acc2[2][1], aa2, b2.y);
            ffma2(acc2[3][0], aa3, b2.x);  ffma2(acc2[3][1], aa3, b2.y);
        }
        __syncthreads();
    }

    const int col = bn + tx * 4;
    #pragma unroll
    for (int i = 0; i < 4; i++) {
        const int row = bm + ty * 4 + i;
        const float2 c01 = unpack2(acc2[i][0]);
        const float2 c23 = unpack2(acc2[i][1]);
        float4 o;
        o.x = c01.x;  o.y = c01.y;  o.z = c23.x;  o.w = c23.y;
        *reinterpret_cast<float4*>(C + (size_t)row * N + col) = o;
    }
}

// ---------------------------------------------------------------------------
// Split-K reduce + bias
// ---------------------------------------------------------------------------
__global__ __launch_bounds__(256) void reduce_bias_kernel(
    const float* __restrict__ part, RedPtrs rp, int nsl)
{
    const int g = blockIdx.y;
    const int i = blockIdx.x * 256 + threadIdx.x;        // float4 index
    const size_t stride4 = (size_t)(M_ * HID_) / 4;
    const float4* p = reinterpret_cast<const float4*>(part) + (size_t)g * nsl * stride4;

    float4 s = p[i];
    for (int j = 1; j < nsl; j++) {
        const float4 t = p[(size_t)j * stride4 + i];
        s.x += t.x;  s.y += t.y;  s.z += t.z;  s.w += t.w;
    }
    const float4 b4 = reinterpret_cast<const float4*>(rp.bias[g])[i & (HID_ / 4 - 1)];
    s.x += b4.x;  s.y += b4.y;  s.z += b4.z;  s.w += b4.w;
    reinterpret_cast<float4*>(rp.out[g])[i] = s;
}

// ---------------------------------------------------------------------------
// Fused GRPE attention, cp.async-pipelined streaming of spq/spk.
// One CTA per (b,h,s) row. Tile = 32 t's, double-buffered.
//   score[t] = (q_s.(k_t+spq[s,t]) + k_s.spk[s,t]) * scale + abias[s,t]
// ---------------------------------------------------------------------------
__global__ __launch_bounds__(256, 5) void attn_pipe_kernel(
    const float* __restrict__ qh, const float* __restrict__ kh,
    const float* __restrict__ vh, const float* __restrict__ abias,
    const float* __restrict__ spq, const float* __restrict__ spk,
    float* __restrict__ xo)
{
    const int s = blockIdx.x;
    const int h = blockIdx.y;
    const int b = blockIdx.z;
    const int tid = threadIdx.x;
    const int lane = tid & 31;
    const int w = tid >> 5;
    const int half = lane >> 4;
    const int l16 = lane & 15;

    // Stage buffers: [2][TT_ rows x 16 float4-granules] per tensor  (16KB each)
    __shared__ __align__(16) float4 stq[2][TT_ * 16];
    __shared__ __align__(16) float4 stk[2][TT_ * 16];
    __shared__ __align__(16) float sh_q[D_];
    __shared__ __align__(16) float sh_k[D_];
    __shared__ float sc[S_];
    __shared__ float sb[S_];
    __shared__ __align__(16) float pvp[16][D_];
    __shared__ float redm[8], reds[8];

    const int bh = b * H_ + h;
    const size_t rowbase = ((size_t)bh * S_ + s) * (size_t)(S_ * D_);
    const float* gq = spq + rowbase;     // 64KB row, streamed in 8 tiles
    const float* gk = spk + rowbase;

    // ---- issue tile 0 (4 cp.asyncs/thread) ----
    {
        const unsigned int sq0 = smem_u32(&stq[0][0]);
        const unsigned int sk0 = smem_u32(&stk[0][0]);
        cpasync16(sq0 + tid * 16,           gq + tid * 4);
        cpasync16(sq0 + (tid + 256) * 16,   gq + (tid + 256) * 4);
        cpasync16(sk0 + tid * 16,           gk + tid * 4);
        cpasync16(sk0 + (tid + 256) * 16,   gk + (tid + 256) * 4);
    }
    asm volatile("cp.async.commit_group;" ::: "memory");

    // ---- prologue: q/k rows + bias row (overlaps with tile-0 fill) ----
    {
        const float* qrow = qh + (size_t)(b * S_ + s) * HID_ + h * D_;
        const float* krow = kh + (size_t)(b * S_ + s) * HID_ + h * D_;
        if (tid < D_)            sh_q[tid]      = qrow[tid];
        else if (tid < 2 * D_)   sh_k[tid - D_] = krow[tid - D_];
        sb[tid] = abias[((size_t)bh * S_ + s) * S_ + tid];
    }
    __syncthreads();

    const float4 q4 = reinterpret_cast<const float4*>(sh_q)[l16];
    const float4 k4 = reinterpret_cast<const float4*>(sh_k)[l16];
    const unsigned long long q01 = pack2(q4.x, q4.y);
    const unsigned long long q23 = pack2(q4.z, q4.w);
    const unsigned long long k01 = pack2(k4.x, k4.y);
    const unsigned long long k23 = pack2(k4.z, k4.w);

    // ---- pipelined score loop over 8 tiles ----
    for (int j = 0; j < S_ / TT_; j++) {
        const int buf = j & 1;
        if (j + 1 < S_ / TT_) {
            const int nb = (j + 1) & 1;
            const float* gq1 = gq + (j + 1) * TT_ * D_;
            const float* gk1 = gk + (j + 1) * TT_ * D_;
            const unsigned int sq1 = smem_u32(&stq[nb][0]);
            const unsigned int sk1 = smem_u32(&stk[nb][0]);
            cpasync16(sq1 + tid * 16,         gq1 + tid * 4);
            cpasync16(sq1 + (tid + 256) * 16, gq1 + (tid + 256) * 4);
            cpasync16(sk1 + tid * 16,         gk1 + tid * 4);
            cpasync16(sk1 + (tid + 256) * 16, gk1 + (tid + 256) * 4);
        }
        asm volatile("cp.async.commit_group;" ::: "memory");
        asm volatile("cp.async.wait_group 1;" ::: "memory");
        __syncthreads();

        // warp w handles local t in [w*4, w*4+4); half-warp per t, 2 iters.
        const ulonglong2* bq2 = reinterpret_cast<const ulonglong2*>(&stq[buf][0]);
        const ulonglong2* bk2 = reinterpret_cast<const ulonglong2*>(&stk[buf][0]);
        const int tlA = w * 4 + half;
        const int tlB = tlA + 2;
        const int tgA = j * TT_ + tlA;
        const int tgB = j * TT_ + tlB;

        const ulonglong2 kkA = reinterpret_cast<const ulonglong2*>(
            kh + (size_t)(b * S_ + tgA) * HID_ + h * D_)[l16];
        const ulonglong2 kkB = reinterpret_cast<const ulonglong2*>(
            kh + (size_t)(b * S_ + tgB) * HID_ + h * D_)[l16];
        const ulonglong2 aqA = bq2[tlA * 16 + l16];
        const ulonglong2 akA = bk2[tlA * 16 + l16];
        const ulonglong2 aqB = bq2[tlB * 16 + l16];
        const ulonglong2 akB = bk2[tlB * 16 + l16];

        unsigned long long pA = mul2(q01, add2(kkA.x, aqA.x));
        ffma2(pA, q23, add2(kkA.y, aqA.y));
        ffma2(pA, k01, akA.x);
        ffma2(pA, k23, akA.y);
        unsigned long long pB = mul2(q01, add2(kkB.x, aqB.x));
        ffma2(pB, q23, add2(kkB.y, aqB.y));
        ffma2(pB, k01, akB.x);
        ffma2(pB, k23, akB.y);

        const float2 fA = unpack2(pA);
        const float2 fB = unpack2(pB);
        float a = fA.x + fA.y;
        float c = fB.x + fB.y;
        #pragma unroll
        for (int o = 8; o > 0; o >>= 1) {
            a += __shfl_xor_sync(0xffffffffu, a, o);
            c += __shfl_xor_sync(0xffffffffu, c, o);
        }
        if (l16 == 0) {
            sc[tgA] = a * SCALE_ + sb[tgA];
            sc[tgB] = c * SCALE_ + sb[tgB];
        }
        __syncthreads();
    }

    // ---- softmax over 256 scores ----
    const float v0 = sc[tid];
    float m = v0;
    #pragma unroll
    for (int o = 16; o > 0; o >>= 1) m = fmaxf(m, __shfl_xor_sync(0xffffffffu, m, o));
    if (lane == 0) redm[w] = m;
    __syncthreads();
    float gm = redm[0];
    #pragma unroll
    for (int j = 1; j < 8; j++) gm = fmaxf(gm, redm[j]);

    const float e = __expf(v0 - gm);
    sc[tid] = e;
    float sum = e;
    #pragma unroll
    for (int o = 16; o > 0; o >>= 1) sum += __shfl_xor_sync(0xffffffffu, sum, o);
    if (lane == 0) reds[w] = sum;
    __syncthreads();
    float tot = reds[0];
    #pragma unroll
    for (int j = 1; j < 8; j++) tot += reds[j];
    const float inv = 1.0f / tot;

    // ---- P @ V : 16 groups of 16 threads ----
    const int g  = tid >> 4;
    const int ld = tid & 15;
    const float* vbase = vh + (size_t)(b * S_) * HID_ + h * D_;
    unsigned long long acc01 = 0ull, acc23 = 0ull;
    #pragma unroll
    for (int i = 0; i < 16; i++) {
        const int t = g * 16 + i;
        const float wt = sc[t];
        const unsigned long long w2 = pack2(wt, wt);
        const ulonglong2 v2 = reinterpret_cast<const ulonglong2*>(
            vbase + (size_t)t * HID_)[ld];
        ffma2(acc01, w2, v2.x);
        ffma2(acc23, w2, v2.y);
    }
    {
        const float2 a01 = unpack2(acc01);
        const float2 a23 = unpack2(acc23);
        float4 o; o.x = a01.x; o.y = a01.y; o.z = a23.x; o.w = a23.y;
        *reinterpret_cast<float4*>(&pvp[g][ld * 4]) = o;
    }
    __syncthreads();

    const int d  = tid & 63;
    const int gq4 = tid >> 6;
    const float part = pvp[gq4 * 4 + 0][d] + pvp[gq4 * 4 + 1][d]
                     + pvp[gq4 * 4 + 2][d] + pvp[gq4 * 4 + 3][d];
    __syncthreads();
    pvp[gq4][d] = part;
    __syncthreads();

    if (tid < D_) {
        const float r = (pvp[0][tid] + pvp[1][tid] + pvp[2][tid] + pvp[3][tid]) * inv;
        xo[(size_t)(b * S_ + s) * HID_ + h * D_ + tid] = r;
    }
}

// ---------------------------------------------------------------------------
// Launch
// ---------------------------------------------------------------------------
extern "C" void kernel_launch(void* const* d_in, const int* in_sizes, int n_in,
                              void* d_out, int out_size)
{
    const float* q    = (const float*)d_in[0];
    const float* k    = (const float*)d_in[1];
    const float* v    = (const float*)d_in[2];
    const float* ab   = (const float*)d_in[3];
    const float* spq  = (const float*)d_in[4];
    const float* spk  = (const float*)d_in[5];
    const float* Wq   = (const float*)d_in[6];
    const float* bq   = (const float*)d_in[7];
    const float* Wk   = (const float*)d_in[8];
    const float* bk   = (const float*)d_in[9];
    const float* Wv   = (const float*)d_in[10];
    const float* bv   = (const float*)d_in[11];
    const float* Wo   = (const float*)d_in[12];
    const float* bo   = (const float*)d_in[13];
    float* out        = (float*)d_out;

    void *pq = nullptr, *pk = nullptr, *pv = nullptr, *px = nullptr, *pp = nullptr;
    cudaGetSymbolAddress(&pq, g_q);
    cudaGetSymbolAddress(&pk, g_k);
    cudaGetSymbolAddress(&pv, g_v);
    cudaGetSymbolAddress(&px, g_x);
    cudaGetSymbolAddress(&pp, g_part);

    // ---- QKV projections: split-K2, 3 GEMMs in one launch (768 CTAs) ----
    GemmPtrs qkv;
    qkv.A[0] = q;  qkv.A[1] = k;  qkv.A[2] = v;
    qkv.W[0] = Wq; qkv.W[1] = Wk; qkv.W[2] = Wv;
    gemm64_part_kernel<<<dim3(HID_ / 64, M_ / 64, 6), 256>>>(
        qkv, (float*)pp, 2, 256, HID_, HID_);

    RedPtrs r1;
    r1.bias[0] = bq; r1.bias[1] = bk; r1.bias[2] = bv;
    r1.out[0] = (float*)pq; r1.out[1] = (float*)pk; r1.out[2] = (float*)pv;
    reduce_bias_kernel<<<dim3(M_ * HID_ / 4 / 256, 3), 256>>>((const float*)pp, r1, 2);

    // ---- attention: cp.async-pipelined, one CTA per (b,h,s) ----
    const dim3 ga(S_, H_, B_);    // 8192 CTAs
    attn_pipe_kernel<<<ga, 256>>>((const float*)pq, (const float*)pk, (const float*)pv,
                                  ab, spq, spk, (float*)px);

    // ---- O projection: split-K4 (512 CTAs) ----
    GemmPtrs og;
    og.A[0] = (const float*)px; og.A[1] = og.A[0]; og.A[2] = og.A[0];
    og.W[0] = Wo; og.W[1] = Wo; og.W[2] = Wo;
    gemm64_part_kernel<<<dim3(HID_ / 64, M_ / 64, 4), 256>>>(
        og, (float*)pp, 4, 128, HID_, HID_);

    RedPtrs r2;
    r2.bias[0] = bo; r2.bias[1] = bo; r2.bias[2] = bo;
    r2.out[0] = out; r2.out[1] = out; r2.out[2] = out;
    reduce_bias_kernel<<<dim3(M_ * HID_ / 4 / 256, 1), 256>>>((const float*)pp, r2, 4);
}

// round 15
// speedup vs baseline: 1.2225x; 1.0471x over previous
#include <cuda_runtime.h>
#include <cstdint>

// Problem constants
#define B_ 4
#define S_ 256
#define H_ 8
#define D_ 64
#define HID_ 512
#define M_ (B_ * S_)   // 1024 rows for all projections
#define SCALE_ 0.125f
#define TT_ 32         // t-tile per pipeline stage

// Scratch (allocation-free rule: __device__ globals)
__device__ float g_q[M_ * HID_];
__device__ float g_k[M_ * HID_];
__device__ float g_v[M_ * HID_];
__device__ float g_x[M_ * HID_];
__device__ float g_part[4 * M_ * HID_];   // split-K partials (O projection)

// ---------------------------------------------------------------------------
// Packed f32x2 helpers (sm_103a)
// ---------------------------------------------------------------------------
__device__ __forceinline__ unsigned long long pack2(float lo, float hi) {
    unsigned long long r;
    asm("mov.b64 %0, {%1, %2};" : "=l"(r) : "f"(lo), "f"(hi));
    return r;
}
__device__ __forceinline__ float2 unpack2(unsigned long long v) {
    float2 r;
    asm("mov.b64 {%0, %1}, %2;" : "=f"(r.x), "=f"(r.y) : "l"(v));
    return r;
}
__device__ __forceinline__ void ffma2(unsigned long long& d,
                                      unsigned long long a, unsigned long long b) {
    asm("fma.rn.f32x2 %0, %1, %2, %0;" : "+l"(d) : "l"(a), "l"(b));
}
__device__ __forceinline__ unsigned long long add2(unsigned long long a,
                                                   unsigned long long b) {
    unsigned long long r;
    asm("add.rn.f32x2 %0, %1, %2;" : "=l"(r) : "l"(a), "l"(b));
    return r;
}
__device__ __forceinline__ unsigned long long mul2(unsigned long long a,
                                                   unsigned long long b) {
    unsigned long long r;
    asm("mul.rn.f32x2 %0, %1, %2;" : "=l"(r) : "l"(a), "l"(b));
    return r;
}
__device__ __forceinline__ void cpasync16(unsigned int saddr, const void* g) {
    asm volatile("cp.async.cg.shared.global [%0], [%1], 16;" :: "r"(saddr), "l"(g));
}
__device__ __forceinline__ unsigned int smem_u32(const void* p) {
    return (unsigned int)__cvta_generic_to_shared(p);
}

struct G3 {
    const float* A[3];
    const float* W[3];
    const float* bias[3];
    float* C[3];
};
struct RedPtrs {
    const float* bias[3];
    float* out[3];
};

// ---------------------------------------------------------------------------
// GEMM 64x64 tile, BK=16, 4x4/thread, f32x2, double-buffered smem +
// register prefetch (one barrier per BK-step).
// blockIdx.z = gemm * nsl + slice.
//   nsl == 1 : full-K, writes C[gemm] with bias fused.
//   nsl  > 1 : split-K partial, writes part + z*(M_*HID_), no bias.
// ---------------------------------------------------------------------------
__global__ __launch_bounds__(256) void gemm64_db_kernel(
    G3 g, float* __restrict__ part, int nsl, int klen, int N, int K)
{
    const int z    = blockIdx.z;
    const int gemm = z / nsl;
    const int sl   = z - gemm * nsl;
    const float* __restrict__ A = g.A[gemm];
    const float* __restrict__ W = g.W[gemm];
    const int k0 = sl * klen;

    __shared__ __align__(16) float As[2][16][64];
    __shared__ __align__(16) float Bs[2][16][64];

    const int bn = blockIdx.x * 64;
    const int bm = blockIdx.y * 64;
    const int tid = threadIdx.x;
    const int tx = tid & 15;
    const int ty = tid >> 4;

    const int aRow = tid >> 2;
    const int aCol = (tid & 3) * 4;
    const int bRow = tid >> 4;
    const int bCol = (tid & 15) * 4;

    unsigned long long acc2[4][2] = {};

    // prefetch k-block 0 into registers, stage into buffer 0
    float4 av = *reinterpret_cast<const float4*>(A + (size_t)(bm + aRow) * K + k0 + aCol);
    float4 bv = *reinterpret_cast<const float4*>(W + (size_t)(k0 + bRow) * N + bn + bCol);
    As[0][aCol + 0][aRow] = av.x;
    As[0][aCol + 1][aRow] = av.y;
    As[0][aCol + 2][aRow] = av.z;
    As[0][aCol + 3][aRow] = av.w;
    *reinterpret_cast<float4*>(&Bs[0][bRow][bCol]) = bv;
    __syncthreads();

    int buf = 0;
    for (int kb = k0; kb < k0 + klen; kb += 16) {
        const int kn = kb + 16;
        const bool more = (kn < k0 + klen);
        if (more) {
            av = *reinterpret_cast<const float4*>(A + (size_t)(bm + aRow) * K + kn + aCol);
            bv = *reinterpret_cast<const float4*>(W + (size_t)(kn + bRow) * N + bn + bCol);
        }

        #pragma unroll
        for (int kk = 0; kk < 16; kk++) {
            const float4 a4 = *reinterpret_cast<const float4*>(&As[buf][kk][ty * 4]);
            const ulonglong2 b2 = *reinterpret_cast<const ulonglong2*>(&Bs[buf][kk][tx * 4]);
            const unsigned long long aa0 = pack2(a4.x, a4.x);
            const unsigned long long aa1 = pack2(a4.y, a4.y);
            const unsigned long long aa2 = pack2(a4.z, a4.z);
            const unsigned long long aa3 = pack2(a4.w, a4.w);
            ffma2(acc2[0][0], aa0, b2.x);  ffma2(acc2[0][1], aa0, b2.y);
            ffma2(acc2[1][0], aa1, b2.x);  ffma2(acc2[1][1], aa1, b2.y);
            ffma2(acc2[2][0], aa2, b2.x);  ffma2(acc2[2][1], aa2, b2.y);
            ffma2(acc2[3][0], aa3, b2.x);  ffma2(acc2[3][1], aa3, b2.y);
        }

        if (more) {
            const int nb = buf ^ 1;
            As[nb][aCol + 0][aRow] = av.x;
            As[nb][aCol + 1][aRow] = av.y;
            As[nb][aCol + 2][aRow] = av.z;
            As[nb][aCol + 3][aRow] = av.w;
            *reinterpret_cast<float4*>(&Bs[nb][bRow][bCol]) = bv;
        }
        __syncthreads();
        buf ^= 1;
    }

    const int col = bn + tx * 4;
    if (nsl == 1) {
        float* __restrict__ C = g.C[gemm];
        const float4 bb = *reinterpret_cast<const float4*>(g.bias[gemm] + col);
        #pragma unroll
        for (int i = 0; i < 4; i++) {
            const int row = bm + ty * 4 + i;
            const float2 c01 = unpack2(acc2[i][0]);
            const float2 c23 = unpack2(acc2[i][1]);
            float4 o;
            o.x = c01.x + bb.x;
            o.y = c01.y + bb.y;
            o.z = c23.x + bb.z;
            o.w = c23.y + bb.w;
            *reinterpret_cast<float4*>(C + (size_t)row * N + col) = o;
        }
    } else {
        float* __restrict__ C = part + (size_t)z * (M_ * HID_);
        #pragma unroll
        for (int i = 0; i < 4; i++) {
            const int row = bm + ty * 4 + i;
            const float2 c01 = unpack2(acc2[i][0]);
            const float2 c23 = unpack2(acc2[i][1]);
            float4 o;
            o.x = c01.x;  o.y = c01.y;  o.z = c23.x;  o.w = c23.y;
            *reinterpret_cast<float4*>(C + (size_t)row * N + col) = o;
        }
    }
}

// ---------------------------------------------------------------------------
// Split-K reduce + bias
// ---------------------------------------------------------------------------
__global__ __launch_bounds__(256) void reduce_bias_kernel(
    const float* __restrict__ part, RedPtrs rp, int nsl)
{
    const int g = blockIdx.y;
    const int i = blockIdx.x * 256 + threadIdx.x;        // float4 index
    const size_t stride4 = (size_t)(M_ * HID_) / 4;
    const float4* p = reinterpret_cast<const float4*>(part) + (size_t)g * nsl * stride4;

    float4 s = p[i];
    for (int j = 1; j < nsl; j++) {
        const float4 t = p[(size_t)j * stride4 + i];
        s.x += t.x;  s.y += t.y;  s.z += t.z;  s.w += t.w;
    }
    const float4 b4 = reinterpret_cast<const float4*>(rp.bias[g])[i & (HID_ / 4 - 1)];
    s.x += b4.x;  s.y += b4.y;  s.z += b4.z;  s.w += b4.w;
    reinterpret_cast<float4*>(rp.out[g])[i] = s;
}

// ---------------------------------------------------------------------------
// Fused GRPE attention, cp.async-pipelined streaming of spq/spk.
// (unchanged from R14 — validated at ~158us, near HBM floor)
// ---------------------------------------------------------------------------
__global__ __launch_bounds__(256, 5) void attn_pipe_kernel(
    const float* __restrict__ qh, const float* __restrict__ kh,
    const float* __restrict__ vh, const float* __restrict__ abias,
    const float* __restrict__ spq, const float* __restrict__ spk,
    float* __restrict__ xo)
{
    const int s = blockIdx.x;
    const int h = blockIdx.y;
    const int b = blockIdx.z;
    const int tid = threadIdx.x;
    const int lane = tid & 31;
    const int w = tid >> 5;
    const int half = lane >> 4;
    const int l16 = lane & 15;

    __shared__ __align__(16) float4 stq[2][TT_ * 16];
    __shared__ __align__(16) float4 stk[2][TT_ * 16];
    __shared__ __align__(16) float sh_q[D_];
    __shared__ __align__(16) float sh_k[D_];
    __shared__ float sc[S_];
    __shared__ float sb[S_];
    __shared__ __align__(16) float pvp[16][D_];
    __shared__ float redm[8], reds[8];

    const int bh = b * H_ + h;
    const size_t rowbase = ((size_t)bh * S_ + s) * (size_t)(S_ * D_);
    const float* gq = spq + rowbase;
    const float* gk = spk + rowbase;

    {
        const unsigned int sq0 = smem_u32(&stq[0][0]);
        const unsigned int sk0 = smem_u32(&stk[0][0]);
        cpasync16(sq0 + tid * 16,           gq + tid * 4);
        cpasync16(sq0 + (tid + 256) * 16,   gq + (tid + 256) * 4);
        cpasync16(sk0 + tid * 16,           gk + tid * 4);
        cpasync16(sk0 + (tid + 256) * 16,   gk + (tid + 256) * 4);
    }
    asm volatile("cp.async.commit_group;" ::: "memory");

    {
        const float* qrow = qh + (size_t)(b * S_ + s) * HID_ + h * D_;
        const float* krow = kh + (size_t)(b * S_ + s) * HID_ + h * D_;
        if (tid < D_)            sh_q[tid]      = qrow[tid];
        else if (tid < 2 * D_)   sh_k[tid - D_] = krow[tid - D_];
        sb[tid] = abias[((size_t)bh * S_ + s) * S_ + tid];
    }
    __syncthreads();

    const float4 q4 = reinterpret_cast<const float4*>(sh_q)[l16];
    const float4 k4 = reinterpret_cast<const float4*>(sh_k)[l16];
    const unsigned long long q01 = pack2(q4.x, q4.y);
    const unsigned long long q23 = pack2(q4.z, q4.w);
    const unsigned long long k01 = pack2(k4.x, k4.y);
    const unsigned long long k23 = pack2(k4.z, k4.w);

    for (int j = 0; j < S_ / TT_; j++) {
        const int buf = j & 1;
        if (j + 1 < S_ / TT_) {
            const int nb = (j + 1) & 1;
            const float* gq1 = gq + (j + 1) * TT_ * D_;
            const float* gk1 = gk + (j + 1) * TT_ * D_;
            const unsigned int sq1 = smem_u32(&stq[nb][0]);
            const unsigned int sk1 = smem_u32(&stk[nb][0]);
            cpasync16(sq1 + tid * 16,         gq1 + tid * 4);
            cpasync16(sq1 + (tid + 256) * 16, gq1 + (tid + 256) * 4);
            cpasync16(sk1 + tid * 16,         gk1 + tid * 4);
            cpasync16(sk1 + (tid + 256) * 16, gk1 + (tid + 256) * 4);
        }
        asm volatile("cp.async.commit_group;" ::: "memory");
        asm volatile("cp.async.wait_group 1;" ::: "memory");
        __syncthreads();

        const ulonglong2* bq2 = reinterpret_cast<const ulonglong2*>(&stq[buf][0]);
        const ulonglong2* bk2 = reinterpret_cast<const ulonglong2*>(&stk[buf][0]);
        const int tlA = w * 4 + half;
        const int tlB = tlA + 2;
        const int tgA = j * TT_ + tlA;
        const int tgB = j * TT_ + tlB;

        const ulonglong2 kkA = reinterpret_cast<const ulonglong2*>(
            kh + (size_t)(b * S_ + tgA) * HID_ + h * D_)[l16];
        const ulonglong2 kkB = reinterpret_cast<const ulonglong2*>(
            kh + (size_t)(b * S_ + tgB) * HID_ + h * D_)[l16];
        const ulonglong2 aqA = bq2[tlA * 16 + l16];
        const ulonglong2 akA = bk2[tlA * 16 + l16];
        const ulonglong2 aqB = bq2[tlB * 16 + l16];
        const ulonglong2 akB = bk2[tlB * 16 + l16];

        unsigned long long pA = mul2(q01, add2(kkA.x, aqA.x));
        ffma2(pA, q23, add2(kkA.y, aqA.y));
        ffma2(pA, k01, akA.x);
        ffma2(pA, k23, akA.y);
        unsigned long long pB = mul2(q01, add2(kkB.x, aqB.x));
        ffma2(pB, q23, add2(kkB.y, aqB.y));
        ffma2(pB, k01, akB.x);
        ffma2(pB, k23, akB.y);

        const float2 fA = unpack2(pA);
        const float2 fB = unpack2(pB);
        float a = fA.x + fA.y;
        float c = fB.x + fB.y;
        #pragma unroll
        for (int o = 8; o > 0; o >>= 1) {
            a += __shfl_xor_sync(0xffffffffu, a, o);
            c += __shfl_xor_sync(0xffffffffu, c, o);
        }
        if (l16 == 0) {
            sc[tgA] = a * SCALE_ + sb[tgA];
            sc[tgB] = c * SCALE_ + sb[tgB];
        }
        __syncthreads();
    }

    const float v0 = sc[tid];
    float m = v0;
    #pragma unroll
    for (int o = 16; o > 0; o >>= 1) m = fmaxf(m, __shfl_xor_sync(0xffffffffu, m, o));
    if (lane == 0) redm[w] = m;
    __syncthreads();
    float gm = redm[0];
    #pragma unroll
    for (int j = 1; j < 8; j++) gm = fmaxf(gm, redm[j]);

    const float e = __expf(v0 - gm);
    sc[tid] = e;
    float sum = e;
    #pragma unroll
    for (int o = 16; o > 0; o >>= 1) sum += __shfl_xor_sync(0xffffffffu, sum, o);
    if (lane == 0) reds[w] = sum;
    __syncthreads();
    float tot = reds[0];
    #pragma unroll
    for (int j = 1; j < 8; j++) tot += reds[j];
    const float inv = 1.0f / tot;

    const int g  = tid >> 4;
    const int ld = tid & 15;
    const float* vbase = vh + (size_t)(b * S_) * HID_ + h * D_;
    unsigned long long acc01 = 0ull, acc23 = 0ull;
    #pragma unroll
    for (int i = 0; i < 16; i++) {
        const int t = g * 16 + i;
        const float wt = sc[t];
        const unsigned long long w2 = pack2(wt, wt);
        const ulonglong2 v2 = reinterpret_cast<const ulonglong2*>(
            vbase + (size_t)t * HID_)[ld];
        ffma2(acc01, w2, v2.x);
        ffma2(acc23, w2, v2.y);
    }
    {
        const float2 a01 = unpack2(acc01);
        const float2 a23 = unpack2(acc23);
        float4 o; o.x = a01.x; o.y = a01.y; o.z = a23.x; o.w = a23.y;
        *reinterpret_cast<float4*>(&pvp[g][ld * 4]) = o;
    }
    __syncthreads();

    const int d  = tid & 63;
    const int gq4 = tid >> 6;
    const float part = pvp[gq4 * 4 + 0][d] + pvp[gq4 * 4 + 1][d]
                     + pvp[gq4 * 4 + 2][d] + pvp[gq4 * 4 + 3][d];
    __syncthreads();
    pvp[gq4][d] = part;
    __syncthreads();

    if (tid < D_) {
        const float r = (pvp[0][tid] + pvp[1][tid] + pvp[2][tid] + pvp[3][tid]) * inv;
        xo[(size_t)(b * S_ + s) * HID_ + h * D_ + tid] = r;
    }
}

// ---------------------------------------------------------------------------
// Launch  (4 launches/call: qkv, attn, o-part, o-reduce)
// ---------------------------------------------------------------------------
extern "C" void kernel_launch(void* const* d_in, const int* in_sizes, int n_in,
                              void* d_out, int out_size)
{
    const float* q    = (const float*)d_in[0];
    const float* k    = (const float*)d_in[1];
    const float* v    = (const float*)d_in[2];
    const float* ab   = (const float*)d_in[3];
    const float* spq  = (const float*)d_in[4];
    const float* spk  = (const float*)d_in[5];
    const float* Wq   = (const float*)d_in[6];
    const float* bq   = (const float*)d_in[7];
    const float* Wk   = (const float*)d_in[8];
    const float* bk   = (const float*)d_in[9];
    const float* Wv   = (const float*)d_in[10];
    const float* bv   = (const float*)d_in[11];
    const float* Wo   = (const float*)d_in[12];
    const float* bo   = (const float*)d_in[13];
    float* out        = (float*)d_out;

    void *pq = nullptr, *pk = nullptr, *pv = nullptr, *px = nullptr, *pp = nullptr;
    cudaGetSymbolAddress(&pq, g_q);
    cudaGetSymbolAddress(&pk, g_k);
    cudaGetSymbolAddress(&pv, g_v);
    cudaGetSymbolAddress(&px, g_x);
    cudaGetSymbolAddress(&pp, g_part);

    // ---- QKV projections: full-K, bias fused, one launch (384 CTAs) ----
    G3 qkv;
    qkv.A[0] = q;  qkv.A[1] = k;  qkv.A[2] = v;
    qkv.W[0] = Wq; qkv.W[1] = Wk; qkv.W[2] = Wv;
    qkv.bias[0] = bq; qkv.bias[1] = bk; qkv.bias[2] = bv;
    qkv.C[0] = (float*)pq; qkv.C[1] = (float*)pk; qkv.C[2] = (float*)pv;
    gemm64_db_kernel<<<dim3(HID_ / 64, M_ / 64, 3), 256>>>(
        qkv, (float*)pp, 1, 512, HID_, HID_);

    // ---- attention: cp.async-pipelined, one CTA per (b,h,s) ----
    const dim3 ga(S_, H_, B_);    // 8192 CTAs
    attn_pipe_kernel<<<ga, 256>>>((const float*)pq, (const float*)pk, (const float*)pv,
                                  ab, spq, spk, (float*)px);

    // ---- O projection: split-K4 (512 CTAs) + reduce ----
    G3 og;
    og.A[0] = (const float*)px; og.A[1] = og.A[0]; og.A[2] = og.A[0];
    og.W[0] = Wo; og.W[1] = Wo; og.W[2] = Wo;
    og.bias[0] = bo; og.bias[1] = bo; og.bias[2] = bo;
    og.C[0] = out; og.C[1] = out; og.C[2] = out;
    gemm64_db_kernel<<<dim3(HID_ / 64, M_ / 64, 4), 256>>>(
        og, (float*)pp, 4, 128, HID_, HID_);

    RedPtrs r2;
    r2.bias[0] = bo; r2.bias[1] = bo; r2.bias[2] = bo;
    r2.out[0] = out; r2.out[1] = out; r2.out[2] = out;
    reduce_bias_kernel<<<dim3(M_ * HID_ / 4 / 256, 1), 256>>>((const float*)pp, r2, 4);
}